// round 7
// baseline (speedup 1.0000x reference)
#include <cuda_runtime.h>
#include <math.h>
#include <stdint.h>

#define S 1024
#define SS (S*S)
#define NBH 4096
#define CAP 512
#define TARGETN 512u
#define MAXR 256
#define NKP 17
#define HOTCAP 8192
#define NW 16               // CAP/32 bitset words
#define FULL 0xFFFFFFFFu

#define HOTB  0x3F733333u   // __float_as_uint(0.95f)
#define HRNG  (0x3F800000u - 0x3F733333u)

// ---------------- scratch (static __device__, zero at module load) ----------
__device__ unsigned int       g_hist[NBH];
__device__ unsigned int       g_cnt_hot;
__device__ unsigned long long g_hot[HOTCAP];   // hot candidates (bits<<32 | ~idx)

static __device__ __forceinline__ unsigned bucket_hot(unsigned bits) {
    unsigned d = bits - HOTB;
    unsigned b = (unsigned)(((unsigned long long)d * NBH) / HRNG);
    return b >= NBH ? (NBH - 1) : b;
}

// ---------------- K1: scan heatmap; keep only conf>=0.95 candidates ---------
__global__ void __launch_bounds__(512) k_scan(const float* __restrict__ x) {
    const float4* __restrict__ x4 = (const float4*)x;
    int i = blockIdx.x * blockDim.x + threadIdx.x;   // exactly SS/4 threads
    int lane = threadIdx.x & 31;

    float4 v4 = x4[i];
    float vs[4] = {v4.x, v4.y, v4.z, v4.w};
    unsigned long long keys[4];
    unsigned bbits[4];
    int cnt = 0;
    #pragma unroll
    for (int c = 0; c < 4; c++) {
        float v = vs[c];
        if (v > 2.9f) {  // prefilter; exact test on conf bits below
            float conf = 1.0f / (1.0f + expf(-v));   // same formula as reference
            unsigned bits = __float_as_uint(conf);
            if (bits >= HOTB) {
                int idx = 4 * i + c;
                keys[cnt]  = ((unsigned long long)bits << 32) | (unsigned)(~idx);
                bbits[cnt] = bits;
                cnt++;
            }
        }
    }
    unsigned pre = (unsigned)cnt;
    #pragma unroll
    for (int off = 1; off < 32; off <<= 1) {
        unsigned v = __shfl_up_sync(FULL, pre, off);
        if (lane >= off) pre += v;
    }
    unsigned total = __shfl_sync(FULL, pre, 31);
    if (total) {
        unsigned base = 0;
        if (lane == 31) base = atomicAdd(&g_cnt_hot, total);
        base = __shfl_sync(FULL, base, 31);
        unsigned mybase = base + pre - (unsigned)cnt;
        for (int c = 0; c < cnt; c++) {
            unsigned p = mybase + c;
            if (p < HOTCAP) g_hot[p] = keys[c];
            atomicAdd(&g_hist[bucket_hot(bbits[c])], 1u);   // RED
        }
    }
}

// ---------------- K2: cutoff + collect + reg-sort + matrix-MIS + emit -------
__global__ void __launch_bounds__(1024, 1) k_mid(const float* __restrict__ x,
                                                 float* __restrict__ out) {
    __shared__ unsigned long long sk[CAP];       // 4 KB (collect + sort exchange)
    __shared__ float2  pos[CAP];                 // 4 KB
    __shared__ unsigned s_mtx[CAP][NW];          // 32 KB conflict matrix (triangular)
    __shared__ unsigned cs[1024];
    __shared__ unsigned seg_suf[32];
    __shared__ unsigned s_cut;
    __shared__ unsigned s_cnt;
    __shared__ unsigned s_accw[NW];
    __shared__ int s_selx[MAXR], s_sely[MAXR];
    __shared__ int s_nsel;

    int t = threadIdx.x;
    int lane = t & 31;

    // --- phase A: per-4-bucket partial sums + init ---
    {
        unsigned s = 0;
        #pragma unroll
        for (int b = 0; b < 4; b++) s += g_hist[t * 4 + b];
        cs[t] = s;
        if (t == 0) s_cnt = 0u;
        if (t < CAP) sk[t] = 0ULL;
        if (t < NW) s_accw[t] = 0u;
    }
    __syncthreads();

    // --- phase B: parallel cutoff; collect STRICTLY ABOVE boundary bucket ---
    if (t < 32) {
        unsigned a = 0;
        #pragma unroll
        for (int b = 0; b < 32; b++) a += cs[lane * 32 + b];
        unsigned suf = a;
        #pragma unroll
        for (int off = 1; off < 32; off <<= 1) {
            unsigned v = __shfl_down_sync(FULL, suf, off);
            if (lane + off < 32) suf += v;
        }
        seg_suf[lane] = suf;
        __syncwarp(FULL);
        unsigned bal = __ballot_sync(FULL, suf >= TARGETN);
        if (lane == 0) {
            if (bal == 0u) { s_cut = 0u; }  // total hot < TARGETN: keep all
            else {
                int lseg = 31 - __clz(bal);
                unsigned base = (lseg < 31) ? seg_suf[lseg + 1] : 0u;
                unsigned cum = base;
                int ccut = lseg * 32;
                for (int c = lseg * 32 + 31; c >= lseg * 32; c--) {
                    cum += cs[c];
                    if (cum >= TARGETN) { ccut = c; break; }
                }
                unsigned cc = cum - cs[ccut];
                unsigned h[4];
                #pragma unroll
                for (int b = 0; b < 4; b++) h[b] = g_hist[ccut * 4 + b];
                int bcut = ccut * 4;
                #pragma unroll
                for (int b = 3; b >= 0; b--) {
                    cc += h[b];
                    if (cc >= TARGETN) { bcut = ccut * 4 + b; break; }
                }
                s_cut = (unsigned)bcut + 1u;  // strict-above => count < TARGETN
            }
        }
    }
    __syncthreads();

    // --- phase C: collect above cutoff (warp-aggregated smem append) --------
    {
        unsigned n = min(g_cnt_hot, (unsigned)HOTCAP);
        unsigned cut = s_cut;
        unsigned rounds = (n + 1023u) / 1024u;
        for (unsigned r = 0; r < rounds; r++) {
            unsigned i = r * 1024u + (unsigned)t;
            bool keep = false;
            unsigned long long key = 0ULL;
            if (i < n) {
                key = g_hot[i];
                keep = bucket_hot((unsigned)(key >> 32)) >= cut;
            }
            unsigned bal = __ballot_sync(FULL, keep);
            if (bal) {
                unsigned wcnt = __popc(bal);
                unsigned base = 0;
                if (lane == 0) base = atomicAdd(&s_cnt, wcnt);
                base = __shfl_sync(FULL, base, 0);
                if (keep) {
                    unsigned p = base + __popc(bal & ((1u << lane) - 1u));
                    if (p < CAP) sk[p] = key;
                }
            }
        }
    }
    __syncthreads();

    // --- phase D: register bitonic sort, descending (1 key/thread) ----------
    unsigned long long key = (t < CAP) ? sk[t] : 0ULL;
    for (int k = 2; k <= CAP; k <<= 1) {
        for (int j = k >> 1; j > 0; j >>= 1) {
            unsigned long long other;
            if (j >= 32) {
                if (t < CAP) sk[t] = key;
                __syncthreads();
                other = (t < CAP) ? sk[t ^ j] : key;
                __syncthreads();
            } else {
                other = __shfl_xor_sync(FULL, key, j);
            }
            bool keepMax = (((t & j) == 0) == ((t & k) == 0));
            if (keepMax ? (other > key) : (other < key)) key = other;
        }
    }
    unsigned m = min(s_cnt, (unsigned)CAP);   // (s_cnt stable since phase C)
    if (t < CAP) {
        unsigned idx = ~(unsigned)key;
        pos[t] = make_float2((float)(idx & (S - 1)), (float)(idx >> 10));
    }
    __syncthreads();

    // --- phase E1: build triangular conflict matrix (pair t / t+CAP split) --
    {
        int i   = (t < CAP) ? t : t - CAP;
        int par = (t < CAP) ? 0 : 1;
        if (i < (int)m) {
            float2 p = pos[i];
            int wi = i >> 5;
            int li = i & 31;
            for (int w = par; w <= wi; w += 2) {
                int jmax = (w == wi) ? li : 32;
                unsigned mw = 0u;
                for (int l = 0; l < jmax; l++) {
                    float2 q = pos[w * 32 + l];   // broadcast LDS
                    float dx = p.x - q.x, dy = p.y - q.y;
                    if (dx * dx + dy * dy <= 100.0f) mw |= 1u << l;
                }
                s_mtx[i][w] = mw;
            }
        }
    }
    __syncthreads();

    // --- phase E2: word-serial lexicographic MIS on warp 0 ------------------
    if (t < 32) {
        unsigned accw[NW];
        #pragma unroll
        for (int w = 0; w < NW; w++) accw[w] = 0u;
        int nwords = ((int)m + 31) >> 5;
        for (int w = 0; w < nwords; w++) {
            int i = w * 32 + lane;
            bool valid = (i < (int)m);
            unsigned rej_or = 0u;
            for (int v = 0; v < w; v++)
                rej_or |= (valid ? s_mtx[i][v] : 0u) & accw[v];
            unsigned mlow = valid ? s_mtx[i][w] : 0u;   // lower-lane conflicts
            unsigned alive = __ballot_sync(FULL, valid && rej_or == 0u);
            unsigned deps = mlow & alive;
            bool myund = (alive >> lane) & 1u;
            bool myacc = false;
            unsigned undecided = alive;
            unsigned accepted = 0u;
            while (true) {
                if (myund && (deps & undecided) == 0u) {
                    myund = false;
                    myacc = ((deps & accepted) == 0u);
                }
                unsigned newund = __ballot_sync(FULL, myund);
                accepted = __ballot_sync(FULL, myacc);
                if (newund == 0u) break;
                undecided = newund;
            }
            accw[w] = accepted;
        }
        if (lane < NW) s_accw[lane] = accw[lane];
    }
    __syncthreads();

    // --- extract accepted in rank order, cap MAXR ---
    if (t < (int)m) {
        unsigned aw = s_accw[t >> 5];
        if ((aw >> lane) & 1u) {
            int below = 0;
            int wi = t >> 5;
            for (int w = 0; w < wi; w++) below += __popc(s_accw[w]);
            below += __popc(aw & ((1u << lane) - 1u));
            if (below < MAXR) {
                float2 p = pos[t];
                s_selx[below] = (int)p.x;
                s_sely[below] = (int)p.y;
            }
        }
    }
    if (t == 0) {
        int tot = 0;
        #pragma unroll
        for (int w = 0; w < NW; w++) tot += __popc(s_accw[w]);
        s_nsel = min(tot, MAXR);
    }
    __syncthreads();

    // --- phase F: emit outputs ---
    // out layout (9472 f32): root[256][2] | kp[256][17][2] | valid[256]
    {
        int ns = s_nsel;
        const float Z = 1.41421356237309515f * 1024.0f;  // sqrt(2)*S
        if (t < MAXR) {
            int r = t;
            bool v = (r < ns);
            float fx = v ? (float)s_selx[r] : 0.0f;
            float fy = v ? (float)s_sely[r] : 0.0f;
            out[2 * r]     = fx * 4.0f;
            out[2 * r + 1] = fy * 4.0f;
            out[2 * MAXR + MAXR * 2 * NKP + r] = v ? 1.0f : 0.0f;
        }
        for (int j = t; j < MAXR * NKP; j += 1024) {
            int r = j / NKP, kpi = j - r * NKP;
            float kx = 0.0f, ky = 0.0f;
            if (r < ns) {
                int xi = s_selx[r], yi = s_sely[r];
                int off = yi * S + xi;
                float dx = tanhf(x[(1 + 2 * kpi) * SS + off]);
                float dy = tanhf(x[(2 + 2 * kpi) * SS + off]);
                float ddx = dx * Z, ddy = dy * Z;
                kx = ddx + (float)xi;
                ky = ddy + (float)yi;
                float d = sqrtf(ddx * ddx + ddy * ddy);
                if (d < 2.0f) { kx = 0.0f; ky = 0.0f; }
                kx *= 4.0f; ky *= 4.0f;
            }
            out[2 * MAXR + 2 * j]     = kx;
            out[2 * MAXR + 2 * j + 1] = ky;
        }
    }

    // --- phase G: cleanup for next graph replay ---
    #pragma unroll
    for (int b = 0; b < NBH / 1024; b++) g_hist[b * 1024 + t] = 0u;
    if (t == 0) g_cnt_hot = 0u;
}

// ---------------- entry ----------------
extern "C" void kernel_launch(void* const* d_in, const int* in_sizes, int n_in,
                              void* d_out, int out_size) {
    const float* x = (const float*)d_in[0];
    float* out = (float*)d_out;
    (void)in_sizes; (void)n_in; (void)out_size;

    k_scan<<<SS / 4 / 512, 512>>>(x);
    k_mid<<<1, 1024>>>(x, out);
}